// round 10
// baseline (speedup 1.0000x reference)
#include <cuda_runtime.h>
#include <cuda_fp16.h>
#include <math.h>
#include <stdint.h>

#define NN 4096
#define FF 512
#define RR 64
#define HH 8
#define HR 512          // H*R
#define EPSB 0.01f
#define ALPHA 0.2f
#define CAP 192         // max neighbors per row (mean 41, max ~70)

// ---------------------------------------------------------------------------
// Device scratch (allocation-free per harness rules)
// ---------------------------------------------------------------------------
__device__ __align__(16) __half g_hidden_h[NN * HR];   // [n][h*64+r] fp16, 4 MB
__device__ __align__(16) float g_asrc[HH * NN];        // [h][n]
__device__ __align__(16) float g_adstT[NN * HH];       // [n][h]
__device__ __align__(16) int   g_nbr[NN * CAP];        // 3 MB edge lists
__device__ __align__(16) float g_p[NN * HH * CAP];     // 25 MB edge probs [i][h][k]
__device__ float g_suminv[NN * HH];
__device__ int   g_cnt[NN];
// fp16 hi/lo GEMM operands in m16n8k16 fragment layout
__device__ uint4 g_Ahi[NN * FF / 8];   // 4 MB
__device__ uint4 g_Alo[NN * FF / 8];   // 4 MB
__device__ uint2 g_Bhi[HR * FF / 4];   // 512 KB
__device__ uint2 g_Blo[HR * FF / 4];   // 512 KB

// ---------------------------------------------------------------------------
// helpers
// ---------------------------------------------------------------------------
static __device__ __forceinline__ void cpa16(void* dst, const void* src) {
    uint32_t d = (uint32_t)__cvta_generic_to_shared(dst);
    asm volatile("cp.async.cg.shared.global [%0], [%1], 16;" :: "r"(d), "l"(src));
}
static __device__ __forceinline__ void cp_commit() {
    asm volatile("cp.async.commit_group;" ::: "memory");
}
template <int N_>
static __device__ __forceinline__ void cp_wait() {
    asm volatile("cp.async.wait_group %0;" :: "n"(N_) : "memory");
}
static __device__ __forceinline__ void split2(float x, float y,
                                              uint32_t& hi, uint32_t& lo) {
    __half2 h = __floats2half2_rn(x, y);
    float rx = x - __low2float(h);
    float ry = y - __high2float(h);
    __half2 l = __floats2half2_rn(rx, ry);
    hi = *reinterpret_cast<uint32_t*>(&h);
    lo = *reinterpret_cast<uint32_t*>(&l);
}
static __device__ __forceinline__ void mma16(float* c, const uint32_t* a,
                                             const uint32_t* b) {
    asm volatile(
        "mma.sync.aligned.m16n8k16.row.col.f32.f16.f16.f32 "
        "{%0,%1,%2,%3}, {%4,%5,%6,%7}, {%8,%9}, {%0,%1,%2,%3};"
        : "+f"(c[0]), "+f"(c[1]), "+f"(c[2]), "+f"(c[3])
        : "r"(a[0]), "r"(a[1]), "r"(a[2]), "r"(a[3]), "r"(b[0]), "r"(b[1]));
}

// ---------------------------------------------------------------------------
// Kernel P1: split A (node matrix) into fp16 hi/lo, MMA-fragment layout.
// ---------------------------------------------------------------------------
__global__ __launch_bounds__(256) void preA_kernel(const float* __restrict__ A)
{
    int t = blockIdx.x * 256 + threadIdx.x;      // 262144 total
    int rt = t >> 10, ks = (t >> 5) & 31, ln = t & 31;
    int g = ln >> 2, tr = ln & 3;
    const float* p0 = A + (size_t)(rt * 16 + g) * FF + ks * 16 + tr * 2;
    float2 r0a = *reinterpret_cast<const float2*>(p0);
    float2 r0b = *reinterpret_cast<const float2*>(p0 + 8);
    float2 r1a = *reinterpret_cast<const float2*>(p0 + 8 * FF);
    float2 r1b = *reinterpret_cast<const float2*>(p0 + 8 * FF + 8);
    uint4 hv, lv;
    split2(r0a.x, r0a.y, hv.x, lv.x);
    split2(r1a.x, r1a.y, hv.y, lv.y);
    split2(r0b.x, r0b.y, hv.z, lv.z);
    split2(r1b.x, r1b.y, hv.w, lv.w);
    g_Ahi[t] = hv;
    g_Alo[t] = lv;
}

// ---------------------------------------------------------------------------
// Kernel P2: split + transpose W[h][f][r] -> B fragments (n = h*64+r, k = f).
// ---------------------------------------------------------------------------
__global__ __launch_bounds__(256) void preB_kernel(const float* __restrict__ W)
{
    int t = blockIdx.x * 256 + threadIdx.x;      // 65536 total
    int n8 = t >> 10, ks = (t >> 5) & 31, ln = t & 31;
    int n = n8 * 8 + (ln >> 2);
    int k0 = ks * 16 + (ln & 3) * 2;
    int h = n >> 6, r = n & 63;
    const float* Wp = W + (size_t)h * FF * RR + (size_t)k0 * RR + r;
    float w00 = Wp[0], w01 = Wp[RR], w10 = Wp[8 * RR], w11 = Wp[9 * RR];
    uint2 hv, lv;
    split2(w00, w01, hv.x, lv.x);
    split2(w10, w11, hv.y, lv.y);
    g_Bhi[t] = hv;
    g_Blo[t] = lv;
}

// ---------------------------------------------------------------------------
// Kernel 1: 3xFP16 mma.sync GEMM + fused epilogue (fp16 hidden + src/dst)
// ---------------------------------------------------------------------------
#define STAGE 32768
__global__ __launch_bounds__(256, 1) void gemm_mma_kernel(const float* __restrict__ att)
{
    extern __shared__ char sm[];
    const int tid = threadIdx.x;
    const int lane = tid & 31;
    const int wid = tid >> 5;
    const int grp = lane >> 2;
    const int thr = lane & 3;
    const int warp_m = wid & 3;
    const int warp_n = wid >> 2;
    const int bm = blockIdx.y * 128;
    const int bn = blockIdx.x * 128;
    const int rtg0 = bm >> 4;
    const int n8g0 = bn >> 3;

    auto prefetch = [&](int c, int st) {
        char* sa = sm + st * STAGE;
        #pragma unroll
        for (int q = 0; q < 2; q++) {
            int gidx = tid + q * 256;
            int rt_l = gidx >> 6, ks_l = (gidx >> 5) & 1, ln2 = gidx & 31;
            size_t src = (size_t)(((rtg0 + rt_l) * 32) + (2 * c + ks_l)) * 32 + ln2;
            cpa16(sa + gidx * 16,        &g_Ahi[src]);
            cpa16(sa + 8192 + gidx * 16, &g_Alo[src]);
        }
        #pragma unroll
        for (int q = 0; q < 2; q++) {
            int gidx = tid + q * 256;
            int n8_l = gidx >> 5, ks_l = (gidx >> 4) & 1, lp = gidx & 15;
            size_t src = (size_t)(((n8g0 + n8_l) * 32) + (2 * c + ks_l)) * 32 + 2 * lp;
            cpa16(sa + 16384 + gidx * 16, &g_Bhi[src]);
            cpa16(sa + 24576 + gidx * 16, &g_Blo[src]);
        }
        cp_commit();
    };

    float acc[2][8][4];
    #pragma unroll
    for (int mt = 0; mt < 2; mt++)
        #pragma unroll
        for (int nt = 0; nt < 8; nt++)
            #pragma unroll
            for (int v = 0; v < 4; v++) acc[mt][nt][v] = 0.f;

    prefetch(0, 0);

    #pragma unroll 1
    for (int c = 0; c < FF / 32; c++) {
        const int st = c & 1;
        if (c + 1 < FF / 32) { prefetch(c + 1, st ^ 1); cp_wait<1>(); }
        else                 { cp_wait<0>(); }
        __syncthreads();

        char* sa = sm + st * STAGE;
        #pragma unroll
        for (int ks = 0; ks < 2; ks++) {
            uint32_t bh[8][2], bl[8][2];
            #pragma unroll
            for (int nt = 0; nt < 8; nt++) {
                uint32_t off = (((warp_n * 8 + nt) * 2 + ks) * 32 + lane) * 8;
                uint2 vh = *reinterpret_cast<const uint2*>(sa + 16384 + off);
                uint2 vl = *reinterpret_cast<const uint2*>(sa + 24576 + off);
                bh[nt][0] = vh.x; bh[nt][1] = vh.y;
                bl[nt][0] = vl.x; bl[nt][1] = vl.y;
            }
            #pragma unroll
            for (int mt = 0; mt < 2; mt++) {
                uint32_t aoff = (((warp_m * 2 + mt) * 2 + ks) * 32 + lane) * 16;
                uint4 ah4 = *reinterpret_cast<const uint4*>(sa + aoff);
                uint4 al4 = *reinterpret_cast<const uint4*>(sa + 8192 + aoff);
                uint32_t ah[4] = {ah4.x, ah4.y, ah4.z, ah4.w};
                uint32_t al[4] = {al4.x, al4.y, al4.z, al4.w};
                #pragma unroll
                for (int nt = 0; nt < 8; nt++) {
                    mma16(acc[mt][nt], ah, bh[nt]);
                    mma16(acc[mt][nt], ah, bl[nt]);
                    mma16(acc[mt][nt], al, bh[nt]);
                }
            }
        }
        __syncthreads();
    }

    // ---- epilogue ----
    const int h = blockIdx.x * 2 + warp_n;
    float wS0[8], wS1[8], wD0[8], wD1[8];
    #pragma unroll
    for (int nt = 0; nt < 8; nt++) {
        int r = nt * 8 + thr * 2;
        const float* ah = att + h * (2 * RR);
        wS0[nt] = ah[r];      wS1[nt] = ah[r + 1];
        wD0[nt] = ah[64 + r]; wD1[nt] = ah[64 + r + 1];
    }

    #pragma unroll
    for (int mt = 0; mt < 2; mt++) {
        float ssum[2] = {0.f, 0.f}, dsum[2] = {0.f, 0.f};
        #pragma unroll
        for (int nt = 0; nt < 8; nt++) {
            int row0 = bm + warp_m * 32 + mt * 16 + grp;
            int col  = bn + warp_n * 64 + nt * 8 + thr * 2;
            *reinterpret_cast<__half2*>(&g_hidden_h[(size_t)row0 * HR + col]) =
                __floats2half2_rn(acc[mt][nt][0], acc[mt][nt][1]);
            *reinterpret_cast<__half2*>(&g_hidden_h[(size_t)(row0 + 8) * HR + col]) =
                __floats2half2_rn(acc[mt][nt][2], acc[mt][nt][3]);
            ssum[0] = fmaf(acc[mt][nt][0], wS0[nt], fmaf(acc[mt][nt][1], wS1[nt], ssum[0]));
            dsum[0] = fmaf(acc[mt][nt][0], wD0[nt], fmaf(acc[mt][nt][1], wD1[nt], dsum[0]));
            ssum[1] = fmaf(acc[mt][nt][2], wS0[nt], fmaf(acc[mt][nt][3], wS1[nt], ssum[1]));
            dsum[1] = fmaf(acc[mt][nt][2], wD0[nt], fmaf(acc[mt][nt][3], wD1[nt], dsum[1]));
        }
        #pragma unroll
        for (int hf = 0; hf < 2; hf++) {
            ssum[hf] += __shfl_xor_sync(0xffffffffu, ssum[hf], 1);
            ssum[hf] += __shfl_xor_sync(0xffffffffu, ssum[hf], 2);
            dsum[hf] += __shfl_xor_sync(0xffffffffu, dsum[hf], 1);
            dsum[hf] += __shfl_xor_sync(0xffffffffu, dsum[hf], 2);
        }
        if (thr == 0) {
            #pragma unroll
            for (int hf = 0; hf < 2; hf++) {
                int row = bm + warp_m * 32 + mt * 16 + grp + hf * 8;
                g_asrc[h * NN + row] = ssum[hf];
                g_adstT[row * HH + h] = dsum[hf];
            }
        }
    }
}

// ---------------------------------------------------------------------------
// Kernel E: per-row edge build. 128 threads/block, one block per row.
// Stream adj row (each lane covers exactly one 128B line), deterministic
// compaction, score all 8 heads per edge, write g_nbr/g_p/g_suminv.
// ---------------------------------------------------------------------------
__global__ __launch_bounds__(128) void edge_kernel(
    const float* __restrict__ adj,
    const float* __restrict__ bias)
{
    __shared__ int s_nbr[CAP];
    __shared__ unsigned s_ws[4];
    __shared__ int s_off[4];
    __shared__ int s_cnt;
    __shared__ float s_as[HH];
    __shared__ float s_sums[4][HH];

    const int i = blockIdx.x;
    const int tid = threadIdx.x;
    const int wid = tid >> 5;
    const int lane = tid & 31;

    if (tid < HH) s_as[tid] = g_asrc[tid * NN + i];

    // each thread reads 32 contiguous cols = one 128B line
    const float* row = adj + (size_t)i * NN + tid * 32;
    unsigned mask = 0;
    #pragma unroll
    for (int q = 0; q < 8; q++) {
        float4 v = *reinterpret_cast<const float4*>(row + q * 4);
        mask |= (v.x != 0.f ? 1u : 0u) << (q * 4 + 0);
        mask |= (v.y != 0.f ? 1u : 0u) << (q * 4 + 1);
        mask |= (v.z != 0.f ? 1u : 0u) << (q * 4 + 2);
        mask |= (v.w != 0.f ? 1u : 0u) << (q * 4 + 3);
    }
    int c = __popc(mask);
    int inc = c;
    #pragma unroll
    for (int d = 1; d < 32; d <<= 1) {
        int o = __shfl_up_sync(0xffffffffu, inc, d);
        if (lane >= d) inc += o;
    }
    if (lane == 31) s_ws[wid] = (unsigned)inc;
    __syncthreads();

    if (tid == 0) {
        int a = 0;
        #pragma unroll
        for (int w = 0; w < 4; w++) { s_off[w] = a; a += (int)s_ws[w]; }
        s_cnt = min(a, CAP);
        g_cnt[i] = min(a, CAP);
    }
    __syncthreads();

    {
        int off = s_off[wid] + inc - c;
        unsigned m = mask;
        while (m) {
            int q = __ffs(m) - 1;
            if (off < CAP) s_nbr[off] = tid * 32 + q;
            off++;
            m &= m - 1;
        }
    }
    __syncthreads();

    const int cnt = s_cnt;
    float psum[HH];
    #pragma unroll
    for (int h = 0; h < HH; h++) psum[h] = 0.f;

    for (int k = tid; k < cnt; k += 128) {
        int j = s_nbr[k];
        g_nbr[i * CAP + k] = j;
        float b = EPSB * __ldg(bias + (size_t)i * NN + j);
        float4 a0 = *reinterpret_cast<const float4*>(g_adstT + j * HH);
        float4 a1 = *reinterpret_cast<const float4*>(g_adstT + j * HH + 4);
        float ad[HH] = {a0.x, a0.y, a0.z, a0.w, a1.x, a1.y, a1.z, a1.w};
        #pragma unroll
        for (int h = 0; h < HH; h++) {
            float pre = s_as[h] + ad[h] + b;
            pre = (pre >= 0.f) ? pre : ALPHA * pre;
            float e = __expf(pre);
            g_p[((size_t)i * HH + h) * CAP + k] = e;
            psum[h] += e;
        }
    }

    #pragma unroll
    for (int h = 0; h < HH; h++) {
        #pragma unroll
        for (int d = 16; d; d >>= 1)
            psum[h] += __shfl_xor_sync(0xffffffffu, psum[h], d);
    }
    if (lane == 0) {
        #pragma unroll
        for (int h = 0; h < HH; h++) s_sums[wid][h] = psum[h];
    }
    __syncthreads();
    if (tid < HH) {
        float t = s_sums[0][tid] + s_sums[1][tid] + s_sums[2][tid] + s_sums[3][tid];
        g_suminv[i * HH + tid] = 1.f / t;
    }
}

// ---------------------------------------------------------------------------
// Kernel G: per-row aggregation. 128 threads/block, no smem, no syncs.
// Thread owns (h = tid>>4, 4 cols). Batch-8 independent LDG.64 gathers.
// ---------------------------------------------------------------------------
__global__ __launch_bounds__(128) void agg_kernel(float* __restrict__ out)
{
    const int i = blockIdx.x;
    const int tid = threadIdx.x;
    const int h = tid >> 4;
    const int cnt = g_cnt[i];

    const int* nb = g_nbr + i * CAP;
    const float* pp = g_p + ((size_t)i * HH + h) * CAP;
    const __half* hb = g_hidden_h + tid * 4;

    float4 acc = make_float4(0.f, 0.f, 0.f, 0.f);

    for (int k0 = 0; k0 < cnt; k0 += 8) {
        int jj[8]; float pv[8];
        #pragma unroll
        for (int q = 0; q < 8; q++) {
            int kk = min(k0 + q, cnt - 1);
            jj[q] = __ldg(nb + kk);
            pv[q] = (k0 + q < cnt) ? __ldg(pp + kk) : 0.f;
        }
        uint2 uu[8];
        #pragma unroll
        for (int q = 0; q < 8; q++)
            uu[q] = *reinterpret_cast<const uint2*>(hb + (size_t)jj[q] * HR);
        #pragma unroll
        for (int q = 0; q < 8; q++) {
            float2 f0 = __half22float2(*reinterpret_cast<__half2*>(&uu[q].x));
            float2 f1 = __half22float2(*reinterpret_cast<__half2*>(&uu[q].y));
            acc.x = fmaf(pv[q], f0.x, acc.x);
            acc.y = fmaf(pv[q], f0.y, acc.y);
            acc.z = fmaf(pv[q], f1.x, acc.z);
            acc.w = fmaf(pv[q], f1.y, acc.w);
        }
    }

    float invl = g_suminv[i * HH + h];
    float4 o = make_float4(acc.x * invl, acc.y * invl, acc.z * invl, acc.w * invl);
    *reinterpret_cast<float4*>(out + (size_t)i * HR + tid * 4) = o;
}

// ---------------------------------------------------------------------------
extern "C" void kernel_launch(void* const* d_in, const int* in_sizes, int n_in,
                              void* d_out, int out_size)
{
    const float* node = (const float*)d_in[0];   // [4096,512]
    const float* adj  = (const float*)d_in[1];   // [4096,4096]
    const float* W    = (const float*)d_in[2];   // [8,512,64]
    const float* att  = (const float*)d_in[3];   // [8,128]
    const float* bias = (const float*)d_in[4];   // [4096,4096]
    float* out = (float*)d_out;                  // [4096,512]

    cudaFuncSetAttribute(gemm_mma_kernel,
                         cudaFuncAttributeMaxDynamicSharedMemorySize, 2 * STAGE);

    preA_kernel<<<NN * FF / 8 / 256, 256>>>(node);
    preB_kernel<<<HR * FF / 4 / 256, 256>>>(W);
    gemm_mma_kernel<<<dim3(HR / 128, NN / 128), 256, 2 * STAGE>>>(att);
    edge_kernel<<<NN, 128>>>(adj, bias);
    agg_kernel<<<NN, 128>>>(out);
}

// round 11
// speedup vs baseline: 1.0250x; 1.0250x over previous
#include <cuda_runtime.h>
#include <cuda_fp16.h>
#include <math.h>
#include <stdint.h>

#define NN 4096
#define FF 512
#define RR 64
#define HH 8
#define HR 512          // H*R
#define EPSB 0.01f
#define ALPHA 0.2f

// ---------------------------------------------------------------------------
// Device scratch (allocation-free per harness rules)
// ---------------------------------------------------------------------------
__device__ __align__(16) __half g_hidden_h[NN * HR];   // [n][h*64+r] fp16, 4 MB
__device__ __align__(16) float g_asrc[HH * NN];        // [h][n]
__device__ __align__(16) float g_adstT[NN * HH];       // [n][h]
// fp16 hi/lo GEMM operands in m16n8k16 fragment layout
__device__ uint4 g_Ahi[NN * FF / 8];   // 4 MB
__device__ uint4 g_Alo[NN * FF / 8];   // 4 MB
__device__ uint2 g_Bhi[HR * FF / 4];   // 512 KB
__device__ uint2 g_Blo[HR * FF / 4];   // 512 KB

// ---------------------------------------------------------------------------
// helpers
// ---------------------------------------------------------------------------
static __device__ __forceinline__ void cpa16(void* dst, const void* src) {
    uint32_t d = (uint32_t)__cvta_generic_to_shared(dst);
    asm volatile("cp.async.cg.shared.global [%0], [%1], 16;" :: "r"(d), "l"(src));
}
static __device__ __forceinline__ void cp_commit() {
    asm volatile("cp.async.commit_group;" ::: "memory");
}
template <int N_>
static __device__ __forceinline__ void cp_wait() {
    asm volatile("cp.async.wait_group %0;" :: "n"(N_) : "memory");
}
static __device__ __forceinline__ void split2(float x, float y,
                                              uint32_t& hi, uint32_t& lo) {
    __half2 h = __floats2half2_rn(x, y);
    float rx = x - __low2float(h);
    float ry = y - __high2float(h);
    __half2 l = __floats2half2_rn(rx, ry);
    hi = *reinterpret_cast<uint32_t*>(&h);
    lo = *reinterpret_cast<uint32_t*>(&l);
}
static __device__ __forceinline__ void mma16(float* c, const uint32_t* a,
                                             const uint32_t* b) {
    asm volatile(
        "mma.sync.aligned.m16n8k16.row.col.f32.f16.f16.f32 "
        "{%0,%1,%2,%3}, {%4,%5,%6,%7}, {%8,%9}, {%0,%1,%2,%3};"
        : "+f"(c[0]), "+f"(c[1]), "+f"(c[2]), "+f"(c[3])
        : "r"(a[0]), "r"(a[1]), "r"(a[2]), "r"(a[3]), "r"(b[0]), "r"(b[1]));
}

// ---------------------------------------------------------------------------
// Kernel P1: split A (node matrix) into fp16 hi/lo, MMA-fragment layout.
// ---------------------------------------------------------------------------
__global__ __launch_bounds__(256) void preA_kernel(const float* __restrict__ A)
{
    int t = blockIdx.x * 256 + threadIdx.x;      // 262144 total
    int rt = t >> 10, ks = (t >> 5) & 31, ln = t & 31;
    int g = ln >> 2, tr = ln & 3;
    const float* p0 = A + (size_t)(rt * 16 + g) * FF + ks * 16 + tr * 2;
    float2 r0a = *reinterpret_cast<const float2*>(p0);
    float2 r0b = *reinterpret_cast<const float2*>(p0 + 8);
    float2 r1a = *reinterpret_cast<const float2*>(p0 + 8 * FF);
    float2 r1b = *reinterpret_cast<const float2*>(p0 + 8 * FF + 8);
    uint4 hv, lv;
    split2(r0a.x, r0a.y, hv.x, lv.x);
    split2(r1a.x, r1a.y, hv.y, lv.y);
    split2(r0b.x, r0b.y, hv.z, lv.z);
    split2(r1b.x, r1b.y, hv.w, lv.w);
    g_Ahi[t] = hv;
    g_Alo[t] = lv;
}

// ---------------------------------------------------------------------------
// Kernel P2: split + transpose W[h][f][r] -> B fragments (n = h*64+r, k = f).
// ---------------------------------------------------------------------------
__global__ __launch_bounds__(256) void preB_kernel(const float* __restrict__ W)
{
    int t = blockIdx.x * 256 + threadIdx.x;      // 65536 total
    int n8 = t >> 10, ks = (t >> 5) & 31, ln = t & 31;
    int n = n8 * 8 + (ln >> 2);
    int k0 = ks * 16 + (ln & 3) * 2;
    int h = n >> 6, r = n & 63;
    const float* Wp = W + (size_t)h * FF * RR + (size_t)k0 * RR + r;
    float w00 = Wp[0], w01 = Wp[RR], w10 = Wp[8 * RR], w11 = Wp[9 * RR];
    uint2 hv, lv;
    split2(w00, w01, hv.x, lv.x);
    split2(w10, w11, hv.y, lv.y);
    g_Bhi[t] = hv;
    g_Blo[t] = lv;
}

// ---------------------------------------------------------------------------
// Kernel 1: 3xFP16 mma.sync GEMM + fused epilogue (fp16 hidden + src/dst)
// ---------------------------------------------------------------------------
#define STAGE 32768
__global__ __launch_bounds__(256, 1) void gemm_mma_kernel(const float* __restrict__ att)
{
    extern __shared__ char sm[];
    const int tid = threadIdx.x;
    const int lane = tid & 31;
    const int wid = tid >> 5;
    const int grp = lane >> 2;
    const int thr = lane & 3;
    const int warp_m = wid & 3;
    const int warp_n = wid >> 2;
    const int bm = blockIdx.y * 128;
    const int bn = blockIdx.x * 128;
    const int rtg0 = bm >> 4;
    const int n8g0 = bn >> 3;

    auto prefetch = [&](int c, int st) {
        char* sa = sm + st * STAGE;
        #pragma unroll
        for (int q = 0; q < 2; q++) {
            int gidx = tid + q * 256;
            int rt_l = gidx >> 6, ks_l = (gidx >> 5) & 1, ln2 = gidx & 31;
            size_t src = (size_t)(((rtg0 + rt_l) * 32) + (2 * c + ks_l)) * 32 + ln2;
            cpa16(sa + gidx * 16,        &g_Ahi[src]);
            cpa16(sa + 8192 + gidx * 16, &g_Alo[src]);
        }
        #pragma unroll
        for (int q = 0; q < 2; q++) {
            int gidx = tid + q * 256;
            int n8_l = gidx >> 5, ks_l = (gidx >> 4) & 1, lp = gidx & 15;
            size_t src = (size_t)(((n8g0 + n8_l) * 32) + (2 * c + ks_l)) * 32 + 2 * lp;
            cpa16(sa + 16384 + gidx * 16, &g_Bhi[src]);
            cpa16(sa + 24576 + gidx * 16, &g_Blo[src]);
        }
        cp_commit();
    };

    float acc[2][8][4];
    #pragma unroll
    for (int mt = 0; mt < 2; mt++)
        #pragma unroll
        for (int nt = 0; nt < 8; nt++)
            #pragma unroll
            for (int v = 0; v < 4; v++) acc[mt][nt][v] = 0.f;

    prefetch(0, 0);

    #pragma unroll 1
    for (int c = 0; c < FF / 32; c++) {
        const int st = c & 1;
        if (c + 1 < FF / 32) { prefetch(c + 1, st ^ 1); cp_wait<1>(); }
        else                 { cp_wait<0>(); }
        __syncthreads();

        char* sa = sm + st * STAGE;
        #pragma unroll
        for (int ks = 0; ks < 2; ks++) {
            uint32_t bh[8][2], bl[8][2];
            #pragma unroll
            for (int nt = 0; nt < 8; nt++) {
                uint32_t off = (((warp_n * 8 + nt) * 2 + ks) * 32 + lane) * 8;
                uint2 vh = *reinterpret_cast<const uint2*>(sa + 16384 + off);
                uint2 vl = *reinterpret_cast<const uint2*>(sa + 24576 + off);
                bh[nt][0] = vh.x; bh[nt][1] = vh.y;
                bl[nt][0] = vl.x; bl[nt][1] = vl.y;
            }
            #pragma unroll
            for (int mt = 0; mt < 2; mt++) {
                uint32_t aoff = (((warp_m * 2 + mt) * 2 + ks) * 32 + lane) * 16;
                uint4 ah4 = *reinterpret_cast<const uint4*>(sa + aoff);
                uint4 al4 = *reinterpret_cast<const uint4*>(sa + 8192 + aoff);
                uint32_t ah[4] = {ah4.x, ah4.y, ah4.z, ah4.w};
                uint32_t al[4] = {al4.x, al4.y, al4.z, al4.w};
                #pragma unroll
                for (int nt = 0; nt < 8; nt++) {
                    mma16(acc[mt][nt], ah, bh[nt]);
                    mma16(acc[mt][nt], ah, bl[nt]);
                    mma16(acc[mt][nt], al, bh[nt]);
                }
            }
        }
        __syncthreads();
    }

    // ---- epilogue ----
    const int h = blockIdx.x * 2 + warp_n;
    float wS0[8], wS1[8], wD0[8], wD1[8];
    #pragma unroll
    for (int nt = 0; nt < 8; nt++) {
        int r = nt * 8 + thr * 2;
        const float* ah = att + h * (2 * RR);
        wS0[nt] = ah[r];      wS1[nt] = ah[r + 1];
        wD0[nt] = ah[64 + r]; wD1[nt] = ah[64 + r + 1];
    }

    #pragma unroll
    for (int mt = 0; mt < 2; mt++) {
        float ssum[2] = {0.f, 0.f}, dsum[2] = {0.f, 0.f};
        #pragma unroll
        for (int nt = 0; nt < 8; nt++) {
            int row0 = bm + warp_m * 32 + mt * 16 + grp;
            int col  = bn + warp_n * 64 + nt * 8 + thr * 2;
            *reinterpret_cast<__half2*>(&g_hidden_h[(size_t)row0 * HR + col]) =
                __floats2half2_rn(acc[mt][nt][0], acc[mt][nt][1]);
            *reinterpret_cast<__half2*>(&g_hidden_h[(size_t)(row0 + 8) * HR + col]) =
                __floats2half2_rn(acc[mt][nt][2], acc[mt][nt][3]);
            ssum[0] = fmaf(acc[mt][nt][0], wS0[nt], fmaf(acc[mt][nt][1], wS1[nt], ssum[0]));
            dsum[0] = fmaf(acc[mt][nt][0], wD0[nt], fmaf(acc[mt][nt][1], wD1[nt], dsum[0]));
            ssum[1] = fmaf(acc[mt][nt][2], wS0[nt], fmaf(acc[mt][nt][3], wS1[nt], ssum[1]));
            dsum[1] = fmaf(acc[mt][nt][2], wD0[nt], fmaf(acc[mt][nt][3], wD1[nt], dsum[1]));
        }
        #pragma unroll
        for (int hf = 0; hf < 2; hf++) {
            ssum[hf] += __shfl_xor_sync(0xffffffffu, ssum[hf], 1);
            ssum[hf] += __shfl_xor_sync(0xffffffffu, ssum[hf], 2);
            dsum[hf] += __shfl_xor_sync(0xffffffffu, dsum[hf], 1);
            dsum[hf] += __shfl_xor_sync(0xffffffffu, dsum[hf], 2);
        }
        if (thr == 0) {
            #pragma unroll
            for (int hf = 0; hf < 2; hf++) {
                int row = bm + warp_m * 32 + mt * 16 + grp + hf * 8;
                g_asrc[h * NN + row] = ssum[hf];
                g_adstT[row * HH + h] = dsum[hf];
            }
        }
    }
}

// ---------------------------------------------------------------------------
// Kernel 3: fused sparse GAT attention + aggregation, one block per row i.
// SCHUNK=128 (one chunk in practice). Score: 1 (kk,h) item/thread x2 passes.
// Aggregation: thread = (sub 0..7, 8-col group); warp reads ONE neighbor row
// 512B contiguous per step (coalesced), batch-4 MLP uint4 gathers.
// ---------------------------------------------------------------------------
#define SCHUNK 128
__global__ __launch_bounds__(512) void gat_row_kernel(
    const float* __restrict__ adj,
    const float* __restrict__ bias,
    float* __restrict__ out)
{
    __shared__ int   s_nbr[NN];            // 16 KB; reused as reduce scratch
    __shared__ float s_p[HH * SCHUNK];     // 4 KB
    __shared__ float s_l[HH], s_asrc[HH];
    __shared__ unsigned s_wsum[16], s_woff[16];
    __shared__ int s_L;

    const int i   = blockIdx.x;
    const int tid = threadIdx.x;
    const int wid = tid >> 5;
    const int lane = tid & 31;

    // Phase A: ordered neighbor compaction (deterministic, no atomics)
    const float* adjRow = adj + (size_t)i * NN;
    const int base = tid * 8;
    float4 v0 = *reinterpret_cast<const float4*>(adjRow + base);
    float4 v1 = *reinterpret_cast<const float4*>(adjRow + base + 4);
    unsigned mask = 0;
    mask |= (v0.x != 0.f) ? 1u   : 0u;
    mask |= (v0.y != 0.f) ? 2u   : 0u;
    mask |= (v0.z != 0.f) ? 4u   : 0u;
    mask |= (v0.w != 0.f) ? 8u   : 0u;
    mask |= (v1.x != 0.f) ? 16u  : 0u;
    mask |= (v1.y != 0.f) ? 32u  : 0u;
    mask |= (v1.z != 0.f) ? 64u  : 0u;
    mask |= (v1.w != 0.f) ? 128u : 0u;
    unsigned cnt_t = __popc(mask);

    unsigned inc = cnt_t;
    #pragma unroll
    for (int d = 1; d < 32; d <<= 1) {
        unsigned o = __shfl_up_sync(0xffffffffu, inc, d);
        if (lane >= d) inc += o;
    }
    if (lane == 31) s_wsum[wid] = inc;

    if (tid < 8) { s_l[tid] = 0.f; s_asrc[tid] = g_asrc[tid * NN + i]; }
    __syncthreads();

    if (tid < 32) {
        unsigned v = (tid < 16) ? s_wsum[tid] : 0u;
        unsigned in2 = v;
        #pragma unroll
        for (int d = 1; d < 16; d <<= 1) {
            unsigned o = __shfl_up_sync(0xffffffffu, in2, d);
            if (lane >= d) in2 += o;
        }
        if (tid < 16) s_woff[tid] = in2 - v;
        if (tid == 15) s_L = (int)in2;
    }
    __syncthreads();

    {
        int off = (int)(s_woff[wid] + (inc - cnt_t));
        unsigned m = mask;
        while (m) {
            int q = __ffs(m) - 1;
            s_nbr[off++] = base + q;
            m &= m - 1;
        }
    }
    __syncthreads();

    const int L = s_L;
    const size_t ibase = (size_t)i * NN;
    const int sub = tid >> 6;          // 0..7 neighbor subset
    const int cg  = tid & 63;          // 8-col group: cols cg*8 .. cg*8+7
    const int hAgg = cg >> 3;          // head for aggregation
    const __half* hb = g_hidden_h + cg * 8;
    float acc[8];
    #pragma unroll
    for (int q = 0; q < 8; q++) acc[q] = 0.f;

    for (int c0 = 0; c0 < L; c0 += SCHUNK) {
        const int cnt = min(SCHUNK, L - c0);
        // score phase: one (kk, h) item per thread, 2 passes cover kk<128
        {
            int kk = tid >> 3;
            const int h = tid & 7;
            #pragma unroll
            for (int pass = 0; pass < 2; pass++, kk += 64) {
                float e = 0.f;
                if (kk < cnt) {
                    int j = s_nbr[c0 + kk];
                    float pre = s_asrc[h] + g_adstT[j * HH + h]
                              + EPSB * __ldg(bias + ibase + j);
                    pre = (pre >= 0.f) ? pre : ALPHA * pre;
                    e = __expf(pre);
                }
                s_p[h * SCHUNK + kk] = e;
            }
        }
        __syncthreads();

        // per-head sum (warp w -> head w)
        if (wid < HH) {
            const float* pw = &s_p[wid * SCHUNK];
            float sl = pw[lane] + pw[lane + 32] + pw[lane + 64] + pw[lane + 96];
            #pragma unroll
            for (int d = 16; d; d >>= 1)
                sl += __shfl_xor_sync(0xffffffffu, sl, d);
            if (lane == 0) s_l[wid] += sl;
        }

        // aggregation: batch-4, element stride 8 (subsets)
        const float* ph = &s_p[hAgg * SCHUNK];
        for (int k0 = sub; k0 < cnt; k0 += 32) {
            int jj[4]; float pv[4];
            #pragma unroll
            for (int q = 0; q < 4; q++) {
                int kk = k0 + q * 8;
                int kkc = min(kk, cnt - 1);
                jj[q] = s_nbr[c0 + kkc];
                pv[q] = (kk < cnt) ? ph[kkc] : 0.f;
            }
            uint4 uu[4];
            #pragma unroll
            for (int q = 0; q < 4; q++)
                uu[q] = *reinterpret_cast<const uint4*>(hb + (size_t)jj[q] * HR);
            #pragma unroll
            for (int q = 0; q < 4; q++) {
                float2 f0 = __half22float2(*reinterpret_cast<__half2*>(&uu[q].x));
                float2 f1 = __half22float2(*reinterpret_cast<__half2*>(&uu[q].y));
                float2 f2 = __half22float2(*reinterpret_cast<__half2*>(&uu[q].z));
                float2 f3 = __half22float2(*reinterpret_cast<__half2*>(&uu[q].w));
                acc[0] = fmaf(pv[q], f0.x, acc[0]);
                acc[1] = fmaf(pv[q], f0.y, acc[1]);
                acc[2] = fmaf(pv[q], f1.x, acc[2]);
                acc[3] = fmaf(pv[q], f1.y, acc[3]);
                acc[4] = fmaf(pv[q], f2.x, acc[4]);
                acc[5] = fmaf(pv[q], f2.y, acc[5]);
                acc[6] = fmaf(pv[q], f3.x, acc[6]);
                acc[7] = fmaf(pv[q], f3.y, acc[7]);
            }
        }
        __syncthreads();   // s_p reuse next chunk; also fences s_nbr reads
    }

    // cross-subset reduction: reuse s_nbr as 4096-float scratch
    float* red = reinterpret_cast<float*>(s_nbr);
    #pragma unroll
    for (int q = 0; q < 8; q += 4)
        *reinterpret_cast<float4*>(&red[sub * 512 + cg * 8 + q]) =
            make_float4(acc[q], acc[q + 1], acc[q + 2], acc[q + 3]);
    __syncthreads();
    {
        const int c = tid;                 // output column
        float s = 0.f;
        #pragma unroll
        for (int sb = 0; sb < 8; sb++) s += red[sb * 512 + c];
        out[(size_t)i * HR + c] = s / s_l[c >> 6];
    }
}

// ---------------------------------------------------------------------------
extern "C" void kernel_launch(void* const* d_in, const int* in_sizes, int n_in,
                              void* d_out, int out_size)
{
    const float* node = (const float*)d_in[0];   // [4096,512]
    const float* adj  = (const float*)d_in[1];   // [4096,4096]
    const float* W    = (const float*)d_in[2];   // [8,512,64]
    const float* att  = (const float*)d_in[3];   // [8,128]
    const float* bias = (const float*)d_in[4];   // [4096,4096]
    float* out = (float*)d_out;                  // [4096,512]

    cudaFuncSetAttribute(gemm_mma_kernel,
                         cudaFuncAttributeMaxDynamicSharedMemorySize, 2 * STAGE);

    preA_kernel<<<NN * FF / 8 / 256, 256>>>(node);
    preB_kernel<<<HR * FF / 4 / 256, 256>>>(W);
    gemm_mma_kernel<<<dim3(HR / 128, NN / 128), 256, 2 * STAGE>>>(att);
    gat_row_kernel<<<NN, 512>>>(adj, bias, out);
}

// round 12
// speedup vs baseline: 1.1393x; 1.1115x over previous
#include <cuda_runtime.h>
#include <cuda_fp16.h>
#include <math.h>
#include <stdint.h>

#define NN 4096
#define FF 512
#define RR 64
#define HH 8
#define HR 512          // H*R
#define EPSB 0.01f
#define ALPHA 0.2f

// ---------------------------------------------------------------------------
// Device scratch (allocation-free per harness rules)
// ---------------------------------------------------------------------------
__device__ __align__(16) __half g_hidden_h[NN * HR];   // [n][h*64+r] fp16, 4 MB
__device__ __align__(16) float g_asrc[HH * NN];        // [h][n]
__device__ __align__(16) float g_adstT[NN * HH];       // [n][h]
// fp16 hi/lo GEMM operands in m16n8k16 fragment layout
__device__ uint4 g_Ahi[NN * FF / 8];   // 4 MB
__device__ uint4 g_Alo[NN * FF / 8];   // 4 MB
__device__ uint2 g_Bhi[HR * FF / 4];   // 512 KB
__device__ uint2 g_Blo[HR * FF / 4];   // 512 KB

// ---------------------------------------------------------------------------
// helpers
// ---------------------------------------------------------------------------
static __device__ __forceinline__ void cpa16(void* dst, const void* src) {
    uint32_t d = (uint32_t)__cvta_generic_to_shared(dst);
    asm volatile("cp.async.cg.shared.global [%0], [%1], 16;" :: "r"(d), "l"(src));
}
static __device__ __forceinline__ void cp_commit() {
    asm volatile("cp.async.commit_group;" ::: "memory");
}
template <int N_>
static __device__ __forceinline__ void cp_wait() {
    asm volatile("cp.async.wait_group %0;" :: "n"(N_) : "memory");
}
static __device__ __forceinline__ void split2(float x, float y,
                                              uint32_t& hi, uint32_t& lo) {
    __half2 h = __floats2half2_rn(x, y);
    float rx = x - __low2float(h);
    float ry = y - __high2float(h);
    __half2 l = __floats2half2_rn(rx, ry);
    hi = *reinterpret_cast<uint32_t*>(&h);
    lo = *reinterpret_cast<uint32_t*>(&l);
}
static __device__ __forceinline__ void mma16(float* c, const uint32_t* a,
                                             const uint32_t* b) {
    asm volatile(
        "mma.sync.aligned.m16n8k16.row.col.f32.f16.f16.f32 "
        "{%0,%1,%2,%3}, {%4,%5,%6,%7}, {%8,%9}, {%0,%1,%2,%3};"
        : "+f"(c[0]), "+f"(c[1]), "+f"(c[2]), "+f"(c[3])
        : "r"(a[0]), "r"(a[1]), "r"(a[2]), "r"(a[3]), "r"(b[0]), "r"(b[1]));
}

// ---------------------------------------------------------------------------
// Kernel P: merged split of A (node) and W into fp16 hi/lo fragment layouts.
// Blocks [0, 1024): A path. Blocks [1024, 1280): B path.
// ---------------------------------------------------------------------------
__global__ __launch_bounds__(256) void preAB_kernel(const float* __restrict__ A,
                                                    const float* __restrict__ W)
{
    int tg = blockIdx.x * 256 + threadIdx.x;
    if (tg < NN * FF / 8) {
        int t = tg;                                  // A path (262144)
        int rt = t >> 10, ks = (t >> 5) & 31, ln = t & 31;
        int g = ln >> 2, tr = ln & 3;
        const float* p0 = A + (size_t)(rt * 16 + g) * FF + ks * 16 + tr * 2;
        float2 r0a = *reinterpret_cast<const float2*>(p0);
        float2 r0b = *reinterpret_cast<const float2*>(p0 + 8);
        float2 r1a = *reinterpret_cast<const float2*>(p0 + 8 * FF);
        float2 r1b = *reinterpret_cast<const float2*>(p0 + 8 * FF + 8);
        uint4 hv, lv;
        split2(r0a.x, r0a.y, hv.x, lv.x);
        split2(r1a.x, r1a.y, hv.y, lv.y);
        split2(r0b.x, r0b.y, hv.z, lv.z);
        split2(r1b.x, r1b.y, hv.w, lv.w);
        g_Ahi[t] = hv;
        g_Alo[t] = lv;
    } else {
        int t = tg - NN * FF / 8;                    // B path (65536)
        int n8 = t >> 10, ks = (t >> 5) & 31, ln = t & 31;
        int n = n8 * 8 + (ln >> 2);
        int k0 = ks * 16 + (ln & 3) * 2;
        int h = n >> 6, r = n & 63;
        const float* Wp = W + (size_t)h * FF * RR + (size_t)k0 * RR + r;
        float w00 = Wp[0], w01 = Wp[RR], w10 = Wp[8 * RR], w11 = Wp[9 * RR];
        uint2 hv, lv;
        split2(w00, w01, hv.x, lv.x);
        split2(w10, w11, hv.y, lv.y);
        g_Bhi[t] = hv;
        g_Blo[t] = lv;
    }
}

// ---------------------------------------------------------------------------
// Kernel 1: 3xFP16 mma.sync GEMM + fused epilogue (fp16 hidden + src/dst)
// ---------------------------------------------------------------------------
#define STAGE 32768
__global__ __launch_bounds__(256, 1) void gemm_mma_kernel(const float* __restrict__ att)
{
    extern __shared__ char sm[];
    const int tid = threadIdx.x;
    const int lane = tid & 31;
    const int wid = tid >> 5;
    const int grp = lane >> 2;
    const int thr = lane & 3;
    const int warp_m = wid & 3;
    const int warp_n = wid >> 2;
    const int bm = blockIdx.y * 128;
    const int bn = blockIdx.x * 128;
    const int rtg0 = bm >> 4;
    const int n8g0 = bn >> 3;

    auto prefetch = [&](int c, int st) {
        char* sa = sm + st * STAGE;
        #pragma unroll
        for (int q = 0; q < 2; q++) {
            int gidx = tid + q * 256;
            int rt_l = gidx >> 6, ks_l = (gidx >> 5) & 1, ln2 = gidx & 31;
            size_t src = (size_t)(((rtg0 + rt_l) * 32) + (2 * c + ks_l)) * 32 + ln2;
            cpa16(sa + gidx * 16,        &g_Ahi[src]);
            cpa16(sa + 8192 + gidx * 16, &g_Alo[src]);
        }
        #pragma unroll
        for (int q = 0; q < 2; q++) {
            int gidx = tid + q * 256;
            int n8_l = gidx >> 5, ks_l = (gidx >> 4) & 1, lp = gidx & 15;
            size_t src = (size_t)(((n8g0 + n8_l) * 32) + (2 * c + ks_l)) * 32 + 2 * lp;
            cpa16(sa + 16384 + gidx * 16, &g_Bhi[src]);
            cpa16(sa + 24576 + gidx * 16, &g_Blo[src]);
        }
        cp_commit();
    };

    float acc[2][8][4];
    #pragma unroll
    for (int mt = 0; mt < 2; mt++)
        #pragma unroll
        for (int nt = 0; nt < 8; nt++)
            #pragma unroll
            for (int v = 0; v < 4; v++) acc[mt][nt][v] = 0.f;

    prefetch(0, 0);

    #pragma unroll 1
    for (int c = 0; c < FF / 32; c++) {
        const int st = c & 1;
        if (c + 1 < FF / 32) { prefetch(c + 1, st ^ 1); cp_wait<1>(); }
        else                 { cp_wait<0>(); }
        __syncthreads();

        char* sa = sm + st * STAGE;
        #pragma unroll
        for (int ks = 0; ks < 2; ks++) {
            uint32_t bh[8][2], bl[8][2];
            #pragma unroll
            for (int nt = 0; nt < 8; nt++) {
                uint32_t off = (((warp_n * 8 + nt) * 2 + ks) * 32 + lane) * 8;
                uint2 vh = *reinterpret_cast<const uint2*>(sa + 16384 + off);
                uint2 vl = *reinterpret_cast<const uint2*>(sa + 24576 + off);
                bh[nt][0] = vh.x; bh[nt][1] = vh.y;
                bl[nt][0] = vl.x; bl[nt][1] = vl.y;
            }
            #pragma unroll
            for (int mt = 0; mt < 2; mt++) {
                uint32_t aoff = (((warp_m * 2 + mt) * 2 + ks) * 32 + lane) * 16;
                uint4 ah4 = *reinterpret_cast<const uint4*>(sa + aoff);
                uint4 al4 = *reinterpret_cast<const uint4*>(sa + 8192 + aoff);
                uint32_t ah[4] = {ah4.x, ah4.y, ah4.z, ah4.w};
                uint32_t al[4] = {al4.x, al4.y, al4.z, al4.w};
                #pragma unroll
                for (int nt = 0; nt < 8; nt++) {
                    mma16(acc[mt][nt], ah, bh[nt]);
                    mma16(acc[mt][nt], ah, bl[nt]);
                    mma16(acc[mt][nt], al, bh[nt]);
                }
            }
        }
        __syncthreads();
    }

    // ---- epilogue ----
    const int h = blockIdx.x * 2 + warp_n;
    float wS0[8], wS1[8], wD0[8], wD1[8];
    #pragma unroll
    for (int nt = 0; nt < 8; nt++) {
        int r = nt * 8 + thr * 2;
        const float* ah = att + h * (2 * RR);
        wS0[nt] = ah[r];      wS1[nt] = ah[r + 1];
        wD0[nt] = ah[64 + r]; wD1[nt] = ah[64 + r + 1];
    }

    #pragma unroll
    for (int mt = 0; mt < 2; mt++) {
        float ssum[2] = {0.f, 0.f}, dsum[2] = {0.f, 0.f};
        #pragma unroll
        for (int nt = 0; nt < 8; nt++) {
            int row0 = bm + warp_m * 32 + mt * 16 + grp;
            int col  = bn + warp_n * 64 + nt * 8 + thr * 2;
            *reinterpret_cast<__half2*>(&g_hidden_h[(size_t)row0 * HR + col]) =
                __floats2half2_rn(acc[mt][nt][0], acc[mt][nt][1]);
            *reinterpret_cast<__half2*>(&g_hidden_h[(size_t)(row0 + 8) * HR + col]) =
                __floats2half2_rn(acc[mt][nt][2], acc[mt][nt][3]);
            ssum[0] = fmaf(acc[mt][nt][0], wS0[nt], fmaf(acc[mt][nt][1], wS1[nt], ssum[0]));
            dsum[0] = fmaf(acc[mt][nt][0], wD0[nt], fmaf(acc[mt][nt][1], wD1[nt], dsum[0]));
            ssum[1] = fmaf(acc[mt][nt][2], wS0[nt], fmaf(acc[mt][nt][3], wS1[nt], ssum[1]));
            dsum[1] = fmaf(acc[mt][nt][2], wD0[nt], fmaf(acc[mt][nt][3], wD1[nt], dsum[1]));
        }
        #pragma unroll
        for (int hf = 0; hf < 2; hf++) {
            ssum[hf] += __shfl_xor_sync(0xffffffffu, ssum[hf], 1);
            ssum[hf] += __shfl_xor_sync(0xffffffffu, ssum[hf], 2);
            dsum[hf] += __shfl_xor_sync(0xffffffffu, dsum[hf], 1);
            dsum[hf] += __shfl_xor_sync(0xffffffffu, dsum[hf], 2);
        }
        if (thr == 0) {
            #pragma unroll
            for (int hf = 0; hf < 2; hf++) {
                int row = bm + warp_m * 32 + mt * 16 + grp + hf * 8;
                g_asrc[h * NN + row] = ssum[hf];
                g_adstT[row * HH + h] = dsum[hf];
            }
        }
    }
}

// ---------------------------------------------------------------------------
// Kernel 3: fused sparse GAT attention + aggregation (R9 structure).
// SCHUNK=64 (covers deg to +3.6 sigma in one chunk; loop handles overflow).
// Score: threads 0..127, (kk = tid&63, head-group = tid>>6), 2 bias LDG/edge.
// Aggregation: identical to R9 (4 cols/thread, 4 subsets, batch-4 LDG.64).
// ---------------------------------------------------------------------------
#define SCHUNK 64
__global__ __launch_bounds__(512) void gat_row_kernel(
    const float* __restrict__ adj,
    const float* __restrict__ bias,
    float* __restrict__ out)
{
    __shared__ int   s_nbr[NN];            // 16 KB; tail reused as reduce scratch
    __shared__ __align__(16) float s_p[HH * SCHUNK];   // 2 KB
    __shared__ float s_l[HH], s_asrc[HH];
    __shared__ unsigned s_wsum[16], s_woff[16];
    __shared__ int s_L;

    const int i   = blockIdx.x;
    const int tid = threadIdx.x;
    const int wid = tid >> 5;
    const int lane = tid & 31;

    // Phase A: ordered neighbor compaction (deterministic, no atomics)
    const float* adjRow = adj + (size_t)i * NN;
    const int base = tid * 8;
    float4 v0 = *reinterpret_cast<const float4*>(adjRow + base);
    float4 v1 = *reinterpret_cast<const float4*>(adjRow + base + 4);
    unsigned mask = 0;
    mask |= (v0.x != 0.f) ? 1u   : 0u;
    mask |= (v0.y != 0.f) ? 2u   : 0u;
    mask |= (v0.z != 0.f) ? 4u   : 0u;
    mask |= (v0.w != 0.f) ? 8u   : 0u;
    mask |= (v1.x != 0.f) ? 16u  : 0u;
    mask |= (v1.y != 0.f) ? 32u  : 0u;
    mask |= (v1.z != 0.f) ? 64u  : 0u;
    mask |= (v1.w != 0.f) ? 128u : 0u;
    unsigned cnt_t = __popc(mask);

    unsigned inc = cnt_t;
    #pragma unroll
    for (int d = 1; d < 32; d <<= 1) {
        unsigned o = __shfl_up_sync(0xffffffffu, inc, d);
        if (lane >= d) inc += o;
    }
    if (lane == 31) s_wsum[wid] = inc;

    if (tid < 8) { s_l[tid] = 0.f; s_asrc[tid] = g_asrc[tid * NN + i]; }
    __syncthreads();

    if (tid < 32) {
        unsigned v = (tid < 16) ? s_wsum[tid] : 0u;
        unsigned in2 = v;
        #pragma unroll
        for (int d = 1; d < 16; d <<= 1) {
            unsigned o = __shfl_up_sync(0xffffffffu, in2, d);
            if (lane >= d) in2 += o;
        }
        if (tid < 16) s_woff[tid] = in2 - v;
        if (tid == 15) s_L = (int)in2;
    }
    __syncthreads();

    {
        int off = (int)(s_woff[wid] + (inc - cnt_t));
        unsigned m = mask;
        while (m) {
            int q = __ffs(m) - 1;
            s_nbr[off++] = base + q;
            m &= m - 1;
        }
    }
    __syncthreads();

    const int L = s_L;
    const size_t ibase = (size_t)i * NN;
    const int sub  = tid >> 7;         // 0..3 neighbor subset
    const int hr4  = tid & 127;        // 4-col group of hidden
    const int hAgg = hr4 >> 4;         // head for aggregation
    float4 a4 = make_float4(0.f, 0.f, 0.f, 0.f);

    for (int c0 = 0; c0 < L; c0 += SCHUNK) {
        const int cnt = min(SCHUNK, L - c0);
        // score phase: threads 0..127; kk = tid&63, head group hg = tid>>6
        if (tid < 128) {
            const int kk = tid & 63;
            const int hg = tid >> 6;
            if (kk < cnt) {
                int j = s_nbr[c0 + kk];
                float4 ad = *reinterpret_cast<const float4*>(g_adstT + j * HH + hg * 4);
                float b = EPSB * __ldg(bias + ibase + j);
                const float* adp = &ad.x;
                #pragma unroll
                for (int q = 0; q < 4; q++) {
                    int hh = hg * 4 + q;
                    float pre = s_asrc[hh] + adp[q] + b;
                    pre = (pre >= 0.f) ? pre : ALPHA * pre;
                    s_p[hh * SCHUNK + kk] = __expf(pre);
                }
            } else {
                #pragma unroll
                for (int q = 0; q < 4; q++)
                    s_p[(hg * 4 + q) * SCHUNK + kk] = 0.f;
            }
        }
        __syncthreads();

        // per-head sum (warps 0-7) — runs alongside aggregation
        if (wid < HH) {
            const float* pw = &s_p[wid * SCHUNK];
            float sloc = pw[lane] + pw[lane + 32];
            #pragma unroll
            for (int d = 16; d; d >>= 1)
                sloc += __shfl_xor_sync(0xffffffffu, sloc, d);
            if (lane == 0) s_l[wid] += sloc;
        }

        // aggregation: 4-deep pipeline, 4 independent LDG.64 per iteration
        const float* ph = &s_p[hAgg * SCHUNK];
        const __half* hb = g_hidden_h + hr4 * 4;
        for (int kk0 = sub; kk0 < cnt; kk0 += 16) {
            int jj[4]; float pp[4];
            #pragma unroll
            for (int q = 0; q < 4; q++) {
                int kk = kk0 + q * 4;
                int kkc = min(kk, cnt - 1);
                jj[q] = s_nbr[c0 + kkc];
                pp[q] = (kk < cnt) ? ph[kkc] : 0.f;
            }
            uint2 uu[4];
            #pragma unroll
            for (int q = 0; q < 4; q++)
                uu[q] = *reinterpret_cast<const uint2*>(hb + (size_t)jj[q] * HR);
            #pragma unroll
            for (int q = 0; q < 4; q++) {
                float2 f0 = __half22float2(*reinterpret_cast<__half2*>(&uu[q].x));
                float2 f1 = __half22float2(*reinterpret_cast<__half2*>(&uu[q].y));
                a4.x = fmaf(pp[q], f0.x, a4.x);
                a4.y = fmaf(pp[q], f0.y, a4.y);
                a4.z = fmaf(pp[q], f1.x, a4.z);
                a4.w = fmaf(pp[q], f1.y, a4.w);
            }
        }
        __syncthreads();
    }

    // cross-subset reduction: reuse s_nbr tail as scratch (4 x 128 float4 = 8 KB)
    float4* red = reinterpret_cast<float4*>(s_nbr + 2048);
    red[sub * 128 + hr4] = a4;
    __syncthreads();
    if (tid < 128) {
        float4 r0 = red[tid], r1 = red[128 + tid],
               r2 = red[256 + tid], r3 = red[384 + tid];
        float invl = 1.f / s_l[tid >> 4];
        float4 o;
        o.x = (r0.x + r1.x + r2.x + r3.x) * invl;
        o.y = (r0.y + r1.y + r2.y + r3.y) * invl;
        o.z = (r0.z + r1.z + r2.z + r3.z) * invl;
        o.w = (r0.w + r1.w + r2.w + r3.w) * invl;
        *reinterpret_cast<float4*>(out + (size_t)i * HR + tid * 4) = o;
    }
}

// ---------------------------------------------------------------------------
extern "C" void kernel_launch(void* const* d_in, const int* in_sizes, int n_in,
                              void* d_out, int out_size)
{
    const float* node = (const float*)d_in[0];   // [4096,512]
    const float* adj  = (const float*)d_in[1];   // [4096,4096]
    const float* W    = (const float*)d_in[2];   // [8,512,64]
    const float* att  = (const float*)d_in[3];   // [8,128]
    const float* bias = (const float*)d_in[4];   // [4096,4096]
    float* out = (float*)d_out;                  // [4096,512]

    cudaFuncSetAttribute(gemm_mma_kernel,
                         cudaFuncAttributeMaxDynamicSharedMemorySize, 2 * STAGE);

    preAB_kernel<<<(NN * FF / 8 + HR * FF / 4) / 256, 256>>>(node, W);
    gemm_mma_kernel<<<dim3(HR / 128, NN / 128), 256, 2 * STAGE>>>(att);
    gat_row_kernel<<<NN, 512>>>(adj, bias, out);
}

// round 13
// speedup vs baseline: 1.1719x; 1.0286x over previous
#include <cuda_runtime.h>
#include <cuda_fp16.h>
#include <math.h>
#include <stdint.h>

#define NN 4096
#define FF 512
#define RR 64
#define HH 8
#define HR 512          // H*R
#define EPSB 0.01f
#define ALPHA 0.2f
#define CAP 192         // max neighbors kept per row (deg ~ 41 +- 6.4)

// ---------------------------------------------------------------------------
// Device scratch (allocation-free per harness rules)
// ---------------------------------------------------------------------------
__device__ __align__(16) __half g_hidden_h[NN * HR];   // [n][h*64+r] fp16, 4 MB
__device__ __align__(16) float g_asrc[HH * NN];        // [h][n]
__device__ __align__(16) float g_adstT[NN * HH];       // [n][h]
__device__ __align__(16) int   g_nbr[NN * CAP];        // 3 MB edge lists
__device__ int g_cnt[NN];
// fp16 hi/lo GEMM operands in m16n8k16 fragment layout
__device__ uint4 g_Ahi[NN * FF / 8];   // 4 MB
__device__ uint4 g_Alo[NN * FF / 8];   // 4 MB
__device__ uint2 g_Bhi[HR * FF / 4];   // 512 KB
__device__ uint2 g_Blo[HR * FF / 4];   // 512 KB

// ---------------------------------------------------------------------------
// helpers
// ---------------------------------------------------------------------------
static __device__ __forceinline__ void cpa16(void* dst, const void* src) {
    uint32_t d = (uint32_t)__cvta_generic_to_shared(dst);
    asm volatile("cp.async.cg.shared.global [%0], [%1], 16;" :: "r"(d), "l"(src));
}
static __device__ __forceinline__ void cp_commit() {
    asm volatile("cp.async.commit_group;" ::: "memory");
}
template <int N_>
static __device__ __forceinline__ void cp_wait() {
    asm volatile("cp.async.wait_group %0;" :: "n"(N_) : "memory");
}
static __device__ __forceinline__ void split2(float x, float y,
                                              uint32_t& hi, uint32_t& lo) {
    __half2 h = __floats2half2_rn(x, y);
    float rx = x - __low2float(h);
    float ry = y - __high2float(h);
    __half2 l = __floats2half2_rn(rx, ry);
    hi = *reinterpret_cast<uint32_t*>(&h);
    lo = *reinterpret_cast<uint32_t*>(&l);
}
static __device__ __forceinline__ void mma16(float* c, const uint32_t* a,
                                             const uint32_t* b) {
    asm volatile(
        "mma.sync.aligned.m16n8k16.row.col.f32.f16.f16.f32 "
        "{%0,%1,%2,%3}, {%4,%5,%6,%7}, {%8,%9}, {%0,%1,%2,%3};"
        : "+f"(c[0]), "+f"(c[1]), "+f"(c[2]), "+f"(c[3])
        : "r"(a[0]), "r"(a[1]), "r"(a[2]), "r"(a[3]), "r"(b[0]), "r"(b[1]));
}

// ---------------------------------------------------------------------------
// Kernel C: adjacency compaction. One block (256 thr) per row; each thread
// scans 16 contiguous cols (4 x float4). Deterministic warp+block scan.
// ---------------------------------------------------------------------------
__global__ __launch_bounds__(256) void compact_kernel(const float* __restrict__ adj)
{
    __shared__ unsigned s_ws[8];
    __shared__ int s_off[8];

    const int i = blockIdx.x;
    const int tid = threadIdx.x;
    const int wid = tid >> 5;
    const int lane = tid & 31;

    const float* row = adj + (size_t)i * NN + tid * 16;
    unsigned mask = 0;
    #pragma unroll
    for (int q = 0; q < 4; q++) {
        float4 v = *reinterpret_cast<const float4*>(row + q * 4);
        mask |= (v.x != 0.f ? 1u : 0u) << (q * 4 + 0);
        mask |= (v.y != 0.f ? 1u : 0u) << (q * 4 + 1);
        mask |= (v.z != 0.f ? 1u : 0u) << (q * 4 + 2);
        mask |= (v.w != 0.f ? 1u : 0u) << (q * 4 + 3);
    }
    int c = __popc(mask);
    int inc = c;
    #pragma unroll
    for (int d = 1; d < 32; d <<= 1) {
        int o = __shfl_up_sync(0xffffffffu, inc, d);
        if (lane >= d) inc += o;
    }
    if (lane == 31) s_ws[wid] = (unsigned)inc;
    __syncthreads();

    if (tid == 0) {
        int a = 0;
        #pragma unroll
        for (int w = 0; w < 8; w++) { s_off[w] = a; a += (int)s_ws[w]; }
        g_cnt[i] = min(a, CAP);
    }
    __syncthreads();

    int off = s_off[wid] + inc - c;
    unsigned m = mask;
    while (m) {
        int q = __ffs(m) - 1;
        if (off < CAP) g_nbr[i * CAP + off] = tid * 16 + q;
        off++;
        m &= m - 1;
    }
}

// ---------------------------------------------------------------------------
// Kernel P: merged split of A (node) and W into fp16 hi/lo fragment layouts.
// ---------------------------------------------------------------------------
__global__ __launch_bounds__(256) void preAB_kernel(const float* __restrict__ A,
                                                    const float* __restrict__ W)
{
    int tg = blockIdx.x * 256 + threadIdx.x;
    if (tg < NN * FF / 8) {
        int t = tg;                                  // A path (262144)
        int rt = t >> 10, ks = (t >> 5) & 31, ln = t & 31;
        int g = ln >> 2, tr = ln & 3;
        const float* p0 = A + (size_t)(rt * 16 + g) * FF + ks * 16 + tr * 2;
        float2 r0a = *reinterpret_cast<const float2*>(p0);
        float2 r0b = *reinterpret_cast<const float2*>(p0 + 8);
        float2 r1a = *reinterpret_cast<const float2*>(p0 + 8 * FF);
        float2 r1b = *reinterpret_cast<const float2*>(p0 + 8 * FF + 8);
        uint4 hv, lv;
        split2(r0a.x, r0a.y, hv.x, lv.x);
        split2(r1a.x, r1a.y, hv.y, lv.y);
        split2(r0b.x, r0b.y, hv.z, lv.z);
        split2(r1b.x, r1b.y, hv.w, lv.w);
        g_Ahi[t] = hv;
        g_Alo[t] = lv;
    } else {
        int t = tg - NN * FF / 8;                    // B path (65536)
        int n8 = t >> 10, ks = (t >> 5) & 31, ln = t & 31;
        int n = n8 * 8 + (ln >> 2);
        int k0 = ks * 16 + (ln & 3) * 2;
        int h = n >> 6, r = n & 63;
        const float* Wp = W + (size_t)h * FF * RR + (size_t)k0 * RR + r;
        float w00 = Wp[0], w01 = Wp[RR], w10 = Wp[8 * RR], w11 = Wp[9 * RR];
        uint2 hv, lv;
        split2(w00, w01, hv.x, lv.x);
        split2(w10, w11, hv.y, lv.y);
        g_Bhi[t] = hv;
        g_Blo[t] = lv;
    }
}

// ---------------------------------------------------------------------------
// Kernel 1: 3xFP16 mma.sync GEMM + fused epilogue (fp16 hidden + src/dst)
// ---------------------------------------------------------------------------
#define STAGE 32768
__global__ __launch_bounds__(256, 1) void gemm_mma_kernel(const float* __restrict__ att)
{
    extern __shared__ char sm[];
    const int tid = threadIdx.x;
    const int lane = tid & 31;
    const int wid = tid >> 5;
    const int grp = lane >> 2;
    const int thr = lane & 3;
    const int warp_m = wid & 3;
    const int warp_n = wid >> 2;
    const int bm = blockIdx.y * 128;
    const int bn = blockIdx.x * 128;
    const int rtg0 = bm >> 4;
    const int n8g0 = bn >> 3;

    auto prefetch = [&](int c, int st) {
        char* sa = sm + st * STAGE;
        #pragma unroll
        for (int q = 0; q < 2; q++) {
            int gidx = tid + q * 256;
            int rt_l = gidx >> 6, ks_l = (gidx >> 5) & 1, ln2 = gidx & 31;
            size_t src = (size_t)(((rtg0 + rt_l) * 32) + (2 * c + ks_l)) * 32 + ln2;
            cpa16(sa + gidx * 16,        &g_Ahi[src]);
            cpa16(sa + 8192 + gidx * 16, &g_Alo[src]);
        }
        #pragma unroll
        for (int q = 0; q < 2; q++) {
            int gidx = tid + q * 256;
            int n8_l = gidx >> 5, ks_l = (gidx >> 4) & 1, lp = gidx & 15;
            size_t src = (size_t)(((n8g0 + n8_l) * 32) + (2 * c + ks_l)) * 32 + 2 * lp;
            cpa16(sa + 16384 + gidx * 16, &g_Bhi[src]);
            cpa16(sa + 24576 + gidx * 16, &g_Blo[src]);
        }
        cp_commit();
    };

    float acc[2][8][4];
    #pragma unroll
    for (int mt = 0; mt < 2; mt++)
        #pragma unroll
        for (int nt = 0; nt < 8; nt++)
            #pragma unroll
            for (int v = 0; v < 4; v++) acc[mt][nt][v] = 0.f;

    prefetch(0, 0);

    #pragma unroll 1
    for (int c = 0; c < FF / 32; c++) {
        const int st = c & 1;
        if (c + 1 < FF / 32) { prefetch(c + 1, st ^ 1); cp_wait<1>(); }
        else                 { cp_wait<0>(); }
        __syncthreads();

        char* sa = sm + st * STAGE;
        #pragma unroll
        for (int ks = 0; ks < 2; ks++) {
            uint32_t bh[8][2], bl[8][2];
            #pragma unroll
            for (int nt = 0; nt < 8; nt++) {
                uint32_t off = (((warp_n * 8 + nt) * 2 + ks) * 32 + lane) * 8;
                uint2 vh = *reinterpret_cast<const uint2*>(sa + 16384 + off);
                uint2 vl = *reinterpret_cast<const uint2*>(sa + 24576 + off);
                bh[nt][0] = vh.x; bh[nt][1] = vh.y;
                bl[nt][0] = vl.x; bl[nt][1] = vl.y;
            }
            #pragma unroll
            for (int mt = 0; mt < 2; mt++) {
                uint32_t aoff = (((warp_m * 2 + mt) * 2 + ks) * 32 + lane) * 16;
                uint4 ah4 = *reinterpret_cast<const uint4*>(sa + aoff);
                uint4 al4 = *reinterpret_cast<const uint4*>(sa + 8192 + aoff);
                uint32_t ah[4] = {ah4.x, ah4.y, ah4.z, ah4.w};
                uint32_t al[4] = {al4.x, al4.y, al4.z, al4.w};
                #pragma unroll
                for (int nt = 0; nt < 8; nt++) {
                    mma16(acc[mt][nt], ah, bh[nt]);
                    mma16(acc[mt][nt], ah, bl[nt]);
                    mma16(acc[mt][nt], al, bh[nt]);
                }
            }
        }
        __syncthreads();
    }

    // ---- epilogue ----
    const int h = blockIdx.x * 2 + warp_n;
    float wS0[8], wS1[8], wD0[8], wD1[8];
    #pragma unroll
    for (int nt = 0; nt < 8; nt++) {
        int r = nt * 8 + thr * 2;
        const float* ah = att + h * (2 * RR);
        wS0[nt] = ah[r];      wS1[nt] = ah[r + 1];
        wD0[nt] = ah[64 + r]; wD1[nt] = ah[64 + r + 1];
    }

    #pragma unroll
    for (int mt = 0; mt < 2; mt++) {
        float ssum[2] = {0.f, 0.f}, dsum[2] = {0.f, 0.f};
        #pragma unroll
        for (int nt = 0; nt < 8; nt++) {
            int row0 = bm + warp_m * 32 + mt * 16 + grp;
            int col  = bn + warp_n * 64 + nt * 8 + thr * 2;
            *reinterpret_cast<__half2*>(&g_hidden_h[(size_t)row0 * HR + col]) =
                __floats2half2_rn(acc[mt][nt][0], acc[mt][nt][1]);
            *reinterpret_cast<__half2*>(&g_hidden_h[(size_t)(row0 + 8) * HR + col]) =
                __floats2half2_rn(acc[mt][nt][2], acc[mt][nt][3]);
            ssum[0] = fmaf(acc[mt][nt][0], wS0[nt], fmaf(acc[mt][nt][1], wS1[nt], ssum[0]));
            dsum[0] = fmaf(acc[mt][nt][0], wD0[nt], fmaf(acc[mt][nt][1], wD1[nt], dsum[0]));
            ssum[1] = fmaf(acc[mt][nt][2], wS0[nt], fmaf(acc[mt][nt][3], wS1[nt], ssum[1]));
            dsum[1] = fmaf(acc[mt][nt][2], wD0[nt], fmaf(acc[mt][nt][3], wD1[nt], dsum[1]));
        }
        #pragma unroll
        for (int hf = 0; hf < 2; hf++) {
            ssum[hf] += __shfl_xor_sync(0xffffffffu, ssum[hf], 1);
            ssum[hf] += __shfl_xor_sync(0xffffffffu, ssum[hf], 2);
            dsum[hf] += __shfl_xor_sync(0xffffffffu, dsum[hf], 1);
            dsum[hf] += __shfl_xor_sync(0xffffffffu, dsum[hf], 2);
        }
        if (thr == 0) {
            #pragma unroll
            for (int hf = 0; hf < 2; hf++) {
                int row = bm + warp_m * 32 + mt * 16 + grp + hf * 8;
                g_asrc[h * NN + row] = ssum[hf];
                g_adstT[row * HH + h] = dsum[hf];
            }
        }
    }
}

// ---------------------------------------------------------------------------
// Kernel 3: score + aggregation, one block (256 thr) per row, 8 blocks/SM.
// Neighbor lists come precompacted from compact_kernel.
// ---------------------------------------------------------------------------
#define SCHUNK 64
__global__ __launch_bounds__(256) void gat_row_kernel(
    const float* __restrict__ bias,
    float* __restrict__ out)
{
    __shared__ int   s_nbr[CAP];
    __shared__ __align__(16) float s_p[HH * SCHUNK];   // 2 KB
    __shared__ __align__(16) float s_red[2 * 512];     // 4 KB reduce scratch
    __shared__ float s_l[HH], s_asrc[HH];

    const int i   = blockIdx.x;
    const int tid = threadIdx.x;
    const int wid = tid >> 5;
    const int lane = tid & 31;

    const int cnt_all = g_cnt[i];
    if (tid < cnt_all) s_nbr[tid] = g_nbr[i * CAP + tid];
    if (tid < 8) { s_l[tid] = 0.f; s_asrc[tid] = g_asrc[tid * NN + i]; }
    __syncthreads();

    const size_t ibase = (size_t)i * NN;
    const int sub = tid >> 7;          // 0..1 neighbor subset
    const int hr4 = tid & 127;         // 4-col group of hidden
    const int hAgg = hr4 >> 4;         // head for aggregation
    float4 a4 = make_float4(0.f, 0.f, 0.f, 0.f);

    for (int c0 = 0; c0 < cnt_all; c0 += SCHUNK) {
        const int cnt = min(SCHUNK, cnt_all - c0);
        // score phase: threads 0..127; kk = tid&63, head group hg = tid>>6
        if (tid < 128) {
            const int kk = tid & 63;
            const int hg = tid >> 6;
            if (kk < cnt) {
                int j = s_nbr[c0 + kk];
                float4 ad = *reinterpret_cast<const float4*>(g_adstT + j * HH + hg * 4);
                float b = EPSB * __ldg(bias + ibase + j);
                const float* adp = &ad.x;
                #pragma unroll
                for (int q = 0; q < 4; q++) {
                    int hh = hg * 4 + q;
                    float pre = s_asrc[hh] + adp[q] + b;
                    pre = (pre >= 0.f) ? pre : ALPHA * pre;
                    s_p[hh * SCHUNK + kk] = __expf(pre);
                }
            } else {
                #pragma unroll
                for (int q = 0; q < 4; q++)
                    s_p[(hg * 4 + q) * SCHUNK + kk] = 0.f;
            }
        }
        __syncthreads();

        // per-head sum (warp w -> head w)
        if (wid < HH) {
            const float* pw = &s_p[wid * SCHUNK];
            float sloc = pw[lane] + pw[lane + 32];
            #pragma unroll
            for (int d = 16; d; d >>= 1)
                sloc += __shfl_xor_sync(0xffffffffu, sloc, d);
            if (lane == 0) s_l[wid] += sloc;
        }

        // aggregation: batch-4 independent LDG.64, subset stride 2
        const float* ph = &s_p[hAgg * SCHUNK];
        const __half* hb = g_hidden_h + hr4 * 4;
        for (int kk0 = sub; kk0 < cnt; kk0 += 8) {
            int jj[4]; float pp[4];
            #pragma unroll
            for (int q = 0; q < 4; q++) {
                int kk = kk0 + q * 2;
                int kkc = min(kk, cnt - 1);
                jj[q] = s_nbr[c0 + kkc];
                pp[q] = (kk < cnt) ? ph[kkc] : 0.f;
            }
            uint2 uu[4];
            #pragma unroll
            for (int q = 0; q < 4; q++)
                uu[q] = *reinterpret_cast<const uint2*>(hb + (size_t)jj[q] * HR);
            #pragma unroll
            for (int q = 0; q < 4; q++) {
                float2 f0 = __half22float2(*reinterpret_cast<__half2*>(&uu[q].x));
                float2 f1 = __half22float2(*reinterpret_cast<__half2*>(&uu[q].y));
                a4.x = fmaf(pp[q], f0.x, a4.x);
                a4.y = fmaf(pp[q], f0.y, a4.y);
                a4.z = fmaf(pp[q], f1.x, a4.z);
                a4.w = fmaf(pp[q], f1.y, a4.w);
            }
        }
        __syncthreads();
    }

    // cross-subset reduction (2-way)
    float4* red = reinterpret_cast<float4*>(s_red);
    red[sub * 128 + hr4] = a4;
    __syncthreads();
    if (tid < 128) {
        float4 r0 = red[tid], r1 = red[128 + tid];
        float invl = 1.f / s_l[tid >> 4];
        float4 o;
        o.x = (r0.x + r1.x) * invl;
        o.y = (r0.y + r1.y) * invl;
        o.z = (r0.z + r1.z) * invl;
        o.w = (r0.w + r1.w) * invl;
        *reinterpret_cast<float4*>(out + (size_t)i * HR + tid * 4) = o;
    }
}

// ---------------------------------------------------------------------------
extern "C" void kernel_launch(void* const* d_in, const int* in_sizes, int n_in,
                              void* d_out, int out_size)
{
    const float* node = (const float*)d_in[0];   // [4096,512]
    const float* adj  = (const float*)d_in[1];   // [4096,4096]
    const float* W    = (const float*)d_in[2];   // [8,512,64]
    const float* att  = (const float*)d_in[3];   // [8,128]
    const float* bias = (const float*)d_in[4];   // [4096,4096]
    float* out = (float*)d_out;                  // [4096,512]

    cudaFuncSetAttribute(gemm_mma_kernel,
                         cudaFuncAttributeMaxDynamicSharedMemorySize, 2 * STAGE);

    compact_kernel<<<NN, 256>>>(adj);
    preAB_kernel<<<(NN * FF / 8 + HR * FF / 4) / 256, 256>>>(node, W);
    gemm_mma_kernel<<<dim3(HR / 128, NN / 128), 256, 2 * STAGE>>>(att);
    gat_row_kernel<<<NN, 256>>>(bias, out);
}

// round 14
// speedup vs baseline: 1.2817x; 1.0938x over previous
#include <cuda_runtime.h>
#include <cuda_fp16.h>
#include <math.h>
#include <stdint.h>

#define NN 4096
#define FF 512
#define RR 64
#define HH 8
#define HR 512          // H*R
#define EPSB 0.01f
#define ALPHA 0.2f
#define CAP 192         // max neighbors kept per row (deg ~ 41 +- 6.4)

// ---------------------------------------------------------------------------
// Device scratch (allocation-free per harness rules)
// ---------------------------------------------------------------------------
__device__ __align__(16) __half g_hidden_h[NN * HR];   // [n][h*64+r] fp16, 4 MB
__device__ __align__(16) float g_asrc[HH * NN];        // [h][n]
__device__ __align__(16) float g_adstT[NN * HH];       // [n][h]
__device__ __align__(16) int   g_nbr[NN * CAP];        // 3 MB edge lists
__device__ int g_cnt[NN];
// fp16 hi/lo GEMM operands in m16n8k16 fragment layout
__device__ uint4 g_Ahi[NN * FF / 8];   // 4 MB
__device__ uint4 g_Alo[NN * FF / 8];   // 4 MB
__device__ uint2 g_Bhi[HR * FF / 4];   // 512 KB
__device__ uint2 g_Blo[HR * FF / 4];   // 512 KB

// ---------------------------------------------------------------------------
// helpers
// ---------------------------------------------------------------------------
static __device__ __forceinline__ void cpa16(void* dst, const void* src) {
    uint32_t d = (uint32_t)__cvta_generic_to_shared(dst);
    asm volatile("cp.async.cg.shared.global [%0], [%1], 16;" :: "r"(d), "l"(src));
}
static __device__ __forceinline__ void cp_commit() {
    asm volatile("cp.async.commit_group;" ::: "memory");
}
template <int N_>
static __device__ __forceinline__ void cp_wait() {
    asm volatile("cp.async.wait_group %0;" :: "n"(N_) : "memory");
}
static __device__ __forceinline__ void split2(float x, float y,
                                              uint32_t& hi, uint32_t& lo) {
    __half2 h = __floats2half2_rn(x, y);
    float rx = x - __low2float(h);
    float ry = y - __high2float(h);
    __half2 l = __floats2half2_rn(rx, ry);
    hi = *reinterpret_cast<uint32_t*>(&h);
    lo = *reinterpret_cast<uint32_t*>(&l);
}
static __device__ __forceinline__ void mma16(float* c, const uint32_t* a,
                                             const uint32_t* b) {
    asm volatile(
        "mma.sync.aligned.m16n8k16.row.col.f32.f16.f16.f32 "
        "{%0,%1,%2,%3}, {%4,%5,%6,%7}, {%8,%9}, {%0,%1,%2,%3};"
        : "+f"(c[0]), "+f"(c[1]), "+f"(c[2]), "+f"(c[3])
        : "r"(a[0]), "r"(a[1]), "r"(a[2]), "r"(a[3]), "r"(b[0]), "r"(b[1]));
}

// ---------------------------------------------------------------------------
// Kernel CP: merged compaction + operand split.
// Blocks [0, NN): compact adjacency row (block i).
// Blocks [NN, NN+1280): A/B fp16 hi/lo split (independent, overlaps compact).
// ---------------------------------------------------------------------------
__global__ __launch_bounds__(256) void compact_pre_kernel(
    const float* __restrict__ adj,
    const float* __restrict__ A,
    const float* __restrict__ W)
{
    const int tid = threadIdx.x;
    if (blockIdx.x < NN) {
        // ---- compaction path ----
        __shared__ unsigned s_ws[8];
        __shared__ int s_off[8];
        const int i = blockIdx.x;
        const int wid = tid >> 5;
        const int lane = tid & 31;

        const float* row = adj + (size_t)i * NN + tid * 16;
        unsigned mask = 0;
        #pragma unroll
        for (int q = 0; q < 4; q++) {
            float4 v = *reinterpret_cast<const float4*>(row + q * 4);
            mask |= (v.x != 0.f ? 1u : 0u) << (q * 4 + 0);
            mask |= (v.y != 0.f ? 1u : 0u) << (q * 4 + 1);
            mask |= (v.z != 0.f ? 1u : 0u) << (q * 4 + 2);
            mask |= (v.w != 0.f ? 1u : 0u) << (q * 4 + 3);
        }
        int c = __popc(mask);
        int inc = c;
        #pragma unroll
        for (int d = 1; d < 32; d <<= 1) {
            int o = __shfl_up_sync(0xffffffffu, inc, d);
            if (lane >= d) inc += o;
        }
        if (lane == 31) s_ws[wid] = (unsigned)inc;
        __syncthreads();

        if (tid == 0) {
            int a = 0;
            #pragma unroll
            for (int w = 0; w < 8; w++) { s_off[w] = a; a += (int)s_ws[w]; }
            g_cnt[i] = min(a, CAP);
        }
        __syncthreads();

        int off = s_off[wid] + inc - c;
        unsigned m = mask;
        while (m) {
            int q = __ffs(m) - 1;
            if (off < CAP) g_nbr[i * CAP + off] = tid * 16 + q;
            off++;
            m &= m - 1;
        }
    } else {
        // ---- operand split path ----
        int tg = (blockIdx.x - NN) * 256 + tid;
        if (tg < NN * FF / 8) {
            int t = tg;                                  // A path (262144)
            int rt = t >> 10, ks = (t >> 5) & 31, ln = t & 31;
            int g = ln >> 2, tr = ln & 3;
            const float* p0 = A + (size_t)(rt * 16 + g) * FF + ks * 16 + tr * 2;
            float2 r0a = *reinterpret_cast<const float2*>(p0);
            float2 r0b = *reinterpret_cast<const float2*>(p0 + 8);
            float2 r1a = *reinterpret_cast<const float2*>(p0 + 8 * FF);
            float2 r1b = *reinterpret_cast<const float2*>(p0 + 8 * FF + 8);
            uint4 hv, lv;
            split2(r0a.x, r0a.y, hv.x, lv.x);
            split2(r1a.x, r1a.y, hv.y, lv.y);
            split2(r0b.x, r0b.y, hv.z, lv.z);
            split2(r1b.x, r1b.y, hv.w, lv.w);
            g_Ahi[t] = hv;
            g_Alo[t] = lv;
        } else {
            int t = tg - NN * FF / 8;                    // B path (65536)
            int n8 = t >> 10, ks = (t >> 5) & 31, ln = t & 31;
            int n = n8 * 8 + (ln >> 2);
            int k0 = ks * 16 + (ln & 3) * 2;
            int h = n >> 6, r = n & 63;
            const float* Wp = W + (size_t)h * FF * RR + (size_t)k0 * RR + r;
            float w00 = Wp[0], w01 = Wp[RR], w10 = Wp[8 * RR], w11 = Wp[9 * RR];
            uint2 hv, lv;
            split2(w00, w01, hv.x, lv.x);
            split2(w10, w11, hv.y, lv.y);
            g_Bhi[t] = hv;
            g_Blo[t] = lv;
        }
    }
}

// ---------------------------------------------------------------------------
// Kernel 1: 3xFP16 mma.sync GEMM + fused epilogue (fp16 hidden + src/dst)
// ---------------------------------------------------------------------------
#define STAGE 32768
__global__ __launch_bounds__(256, 1) void gemm_mma_kernel(const float* __restrict__ att)
{
    extern __shared__ char sm[];
    const int tid = threadIdx.x;
    const int lane = tid & 31;
    const int wid = tid >> 5;
    const int grp = lane >> 2;
    const int thr = lane & 3;
    const int warp_m = wid & 3;
    const int warp_n = wid >> 2;
    const int bm = blockIdx.y * 128;
    const int bn = blockIdx.x * 128;
    const int rtg0 = bm >> 4;
    const int n8g0 = bn >> 3;

    auto prefetch = [&](int c, int st) {
        char* sa = sm + st * STAGE;
        #pragma unroll
        for (int q = 0; q < 2; q++) {
            int gidx = tid + q * 256;
            int rt_l = gidx >> 6, ks_l = (gidx >> 5) & 1, ln2 = gidx & 31;
            size_t src = (size_t)(((rtg0 + rt_l) * 32) + (2 * c + ks_l)) * 32 + ln2;
            cpa16(sa + gidx * 16,        &g_Ahi[src]);
            cpa16(sa + 8192 + gidx * 16, &g_Alo[src]);
        }
        #pragma unroll
        for (int q = 0; q < 2; q++) {
            int gidx = tid + q * 256;
            int n8_l = gidx >> 5, ks_l = (gidx >> 4) & 1, lp = gidx & 15;
            size_t src = (size_t)(((n8g0 + n8_l) * 32) + (2 * c + ks_l)) * 32 + 2 * lp;
            cpa16(sa + 16384 + gidx * 16, &g_Bhi[src]);
            cpa16(sa + 24576 + gidx * 16, &g_Blo[src]);
        }
        cp_commit();
    };

    float acc[2][8][4];
    #pragma unroll
    for (int mt = 0; mt < 2; mt++)
        #pragma unroll
        for (int nt = 0; nt < 8; nt++)
            #pragma unroll
            for (int v = 0; v < 4; v++) acc[mt][nt][v] = 0.f;

    prefetch(0, 0);

    #pragma unroll 1
    for (int c = 0; c < FF / 32; c++) {
        const int st = c & 1;
        if (c + 1 < FF / 32) { prefetch(c + 1, st ^ 1); cp_wait<1>(); }
        else                 { cp_wait<0>(); }
        __syncthreads();

        char* sa = sm + st * STAGE;
        #pragma unroll
        for (int ks = 0; ks < 2; ks++) {
            uint32_t bh[8][2], bl[8][2];
            #pragma unroll
            for (int nt = 0; nt < 8; nt++) {
                uint32_t off = (((warp_n * 8 + nt) * 2 + ks) * 32 + lane) * 8;
                uint2 vh = *reinterpret_cast<const uint2*>(sa + 16384 + off);
                uint2 vl = *reinterpret_cast<const uint2*>(sa + 24576 + off);
                bh[nt][0] = vh.x; bh[nt][1] = vh.y;
                bl[nt][0] = vl.x; bl[nt][1] = vl.y;
            }
            #pragma unroll
            for (int mt = 0; mt < 2; mt++) {
                uint32_t aoff = (((warp_m * 2 + mt) * 2 + ks) * 32 + lane) * 16;
                uint4 ah4 = *reinterpret_cast<const uint4*>(sa + aoff);
                uint4 al4 = *reinterpret_cast<const uint4*>(sa + 8192 + aoff);
                uint32_t ah[4] = {ah4.x, ah4.y, ah4.z, ah4.w};
                uint32_t al[4] = {al4.x, al4.y, al4.z, al4.w};
                #pragma unroll
                for (int nt = 0; nt < 8; nt++) {
                    mma16(acc[mt][nt], ah, bh[nt]);
                    mma16(acc[mt][nt], ah, bl[nt]);
                    mma16(acc[mt][nt], al, bh[nt]);
                }
            }
        }
        __syncthreads();
    }

    // ---- epilogue ----
    const int h = blockIdx.x * 2 + warp_n;
    float wS0[8], wS1[8], wD0[8], wD1[8];
    #pragma unroll
    for (int nt = 0; nt < 8; nt++) {
        int r = nt * 8 + thr * 2;
        const float* ah = att + h * (2 * RR);
        wS0[nt] = ah[r];      wS1[nt] = ah[r + 1];
        wD0[nt] = ah[64 + r]; wD1[nt] = ah[64 + r + 1];
    }

    #pragma unroll
    for (int mt = 0; mt < 2; mt++) {
        float ssum[2] = {0.f, 0.f}, dsum[2] = {0.f, 0.f};
        #pragma unroll
        for (int nt = 0; nt < 8; nt++) {
            int row0 = bm + warp_m * 32 + mt * 16 + grp;
            int col  = bn + warp_n * 64 + nt * 8 + thr * 2;
            *reinterpret_cast<__half2*>(&g_hidden_h[(size_t)row0 * HR + col]) =
                __floats2half2_rn(acc[mt][nt][0], acc[mt][nt][1]);
            *reinterpret_cast<__half2*>(&g_hidden_h[(size_t)(row0 + 8) * HR + col]) =
                __floats2half2_rn(acc[mt][nt][2], acc[mt][nt][3]);
            ssum[0] = fmaf(acc[mt][nt][0], wS0[nt], fmaf(acc[mt][nt][1], wS1[nt], ssum[0]));
            dsum[0] = fmaf(acc[mt][nt][0], wD0[nt], fmaf(acc[mt][nt][1], wD1[nt], dsum[0]));
            ssum[1] = fmaf(acc[mt][nt][2], wS0[nt], fmaf(acc[mt][nt][3], wS1[nt], ssum[1]));
            dsum[1] = fmaf(acc[mt][nt][2], wD0[nt], fmaf(acc[mt][nt][3], wD1[nt], dsum[1]));
        }
        #pragma unroll
        for (int hf = 0; hf < 2; hf++) {
            ssum[hf] += __shfl_xor_sync(0xffffffffu, ssum[hf], 1);
            ssum[hf] += __shfl_xor_sync(0xffffffffu, ssum[hf], 2);
            dsum[hf] += __shfl_xor_sync(0xffffffffu, dsum[hf], 1);
            dsum[hf] += __shfl_xor_sync(0xffffffffu, dsum[hf], 2);
        }
        if (thr == 0) {
            #pragma unroll
            for (int hf = 0; hf < 2; hf++) {
                int row = bm + warp_m * 32 + mt * 16 + grp + hf * 8;
                g_asrc[h * NN + row] = ssum[hf];
                g_adstT[row * HH + h] = dsum[hf];
            }
        }
    }
}

// ---------------------------------------------------------------------------
// Kernel 3: score + aggregation, one block (256 thr) per row.
// Aggregation: padded lists (no clamps), uint4 LDG.128 (8 cols/thread),
// 4 subsets, batch-2 independent loads.
// ---------------------------------------------------------------------------
#define SCHUNK 64
__global__ __launch_bounds__(256) void gat_row_kernel(
    const float* __restrict__ bias,
    float* __restrict__ out)
{
    __shared__ int   s_nbr[CAP];
    __shared__ __align__(16) float s_p[HH * SCHUNK];   // 2 KB
    __shared__ __align__(16) float s_red[4 * 512];     // 8 KB reduce scratch
    __shared__ float s_l[HH], s_asrc[HH];

    const int i   = blockIdx.x;
    const int tid = threadIdx.x;
    const int wid = tid >> 5;
    const int lane = tid & 31;

    const int cnt_all = g_cnt[i];
    const int pad_all = (cnt_all + 7) & ~7;
    if (tid < cnt_all)                      s_nbr[tid] = g_nbr[i * CAP + tid];
    else if (tid < pad_all)                 s_nbr[tid] = 0;   // p=0 there
    if (tid < 8) { s_l[tid] = 0.f; s_asrc[tid] = g_asrc[tid * NN + i]; }
    __syncthreads();

    const size_t ibase = (size_t)i * NN;
    const int sub = tid >> 6;          // 0..3 neighbor subset
    const int cg  = tid & 63;          // 8-col group
    const int hAgg = cg >> 3;          // head for aggregation
    float acc[8];
    #pragma unroll
    for (int q = 0; q < 8; q++) acc[q] = 0.f;

    for (int c0 = 0; c0 < cnt_all; c0 += SCHUNK) {
        const int cnt = min(SCHUNK, cnt_all - c0);
        // score phase: threads 0..127; kk = tid&63, head group hg = tid>>6
        if (tid < 128) {
            const int kk = tid & 63;
            const int hg = tid >> 6;
            if (kk < cnt) {
                int j = s_nbr[c0 + kk];
                float4 ad = *reinterpret_cast<const float4*>(g_adstT + j * HH + hg * 4);
                float b = EPSB * __ldg(bias + ibase + j);
                const float* adp = &ad.x;
                #pragma unroll
                for (int q = 0; q < 4; q++) {
                    int hh = hg * 4 + q;
                    float pre = s_asrc[hh] + adp[q] + b;
                    pre = (pre >= 0.f) ? pre : ALPHA * pre;
                    s_p[hh * SCHUNK + kk] = __expf(pre);
                }
            } else {
                #pragma unroll
                for (int q = 0; q < 4; q++)
                    s_p[(hg * 4 + q) * SCHUNK + kk] = 0.f;
            }
        }
        __syncthreads();

        // per-head sum (warp w -> head w)
        if (wid < HH) {
            const float* pw = &s_p[wid * SCHUNK];
            float sloc = pw[lane] + pw[lane + 32];
            #pragma unroll
            for (int d = 16; d; d >>= 1)
                sloc += __shfl_xor_sync(0xffffffffu, sloc, d);
            if (lane == 0) s_l[wid] += sloc;
        }

        // aggregation: padded, clamp-free; 2 independent LDG.128 / iter
        const float* ph = &s_p[hAgg * SCHUNK];
        const __half* hb = g_hidden_h + cg * 8;
        const int cnt_pad = (cnt + 7) & ~7;
        for (int kk0 = sub; kk0 < cnt_pad; kk0 += 8) {
            int j0 = s_nbr[c0 + kk0];
            int j1 = s_nbr[c0 + kk0 + 4];
            float p0 = ph[kk0], p1 = ph[kk0 + 4];
            uint4 u0 = *reinterpret_cast<const uint4*>(hb + (size_t)j0 * HR);
            uint4 u1 = *reinterpret_cast<const uint4*>(hb + (size_t)j1 * HR);
            {
                float2 f0 = __half22float2(*reinterpret_cast<__half2*>(&u0.x));
                float2 f1 = __half22float2(*reinterpret_cast<__half2*>(&u0.y));
                float2 f2 = __half22float2(*reinterpret_cast<__half2*>(&u0.z));
                float2 f3 = __half22float2(*reinterpret_cast<__half2*>(&u0.w));
                acc[0] = fmaf(p0, f0.x, acc[0]); acc[1] = fmaf(p0, f0.y, acc[1]);
                acc[2] = fmaf(p0, f1.x, acc[2]); acc[3] = fmaf(p0, f1.y, acc[3]);
                acc[4] = fmaf(p0, f2.x, acc[4]); acc[5] = fmaf(p0, f2.y, acc[5]);
                acc[6] = fmaf(p0, f3.x, acc[6]); acc[7] = fmaf(p0, f3.y, acc[7]);
            }
            {
                float2 f0 = __half22float2(*reinterpret_cast<__half2*>(&u1.x));
                float2 f1 = __half22float2(*reinterpret_cast<__half2*>(&u1.y));
                float2 f2 = __half22float2(*reinterpret_cast<__half2*>(&u1.z));
                float2 f3 = __half22float2(*reinterpret_cast<__half2*>(&u1.w));
                acc[0] = fmaf(p1, f0.x, acc[0]); acc[1] = fmaf(p1, f0.y, acc[1]);
                acc[2] = fmaf(p1, f1.x, acc[2]); acc[3] = fmaf(p1, f1.y, acc[3]);
                acc[4] = fmaf(p1, f2.x, acc[4]); acc[5] = fmaf(p1, f2.y, acc[5]);
                acc[6] = fmaf(p1, f3.x, acc[6]); acc[7] = fmaf(p1, f3.y, acc[7]);
            }
        }
        __syncthreads();
    }

    // cross-subset reduction (4-way)
    *reinterpret_cast<float4*>(&s_red[sub * 512 + cg * 8]) =
        make_float4(acc[0], acc[1], acc[2], acc[3]);
    *reinterpret_cast<float4*>(&s_red[sub * 512 + cg * 8 + 4]) =
        make_float4(acc[4], acc[5], acc[6], acc[7]);
    __syncthreads();
    if (tid < 128) {
        const float4* red4 = reinterpret_cast<const float4*>(s_red);
        float4 r0 = red4[tid], r1 = red4[128 + tid],
               r2 = red4[256 + tid], r3 = red4[384 + tid];
        float invl = 1.f / s_l[tid >> 4];
        float4 o;
        o.x = (r0.x + r1.x + r2.x + r3.x) * invl;
        o.y = (r0.y + r1.y + r2.y + r3.y) * invl;
        o.z = (r0.z + r1.z + r2.z + r3.z) * invl;
        o.w = (r0.w + r1.w + r2.w + r3.w) * invl;
        *reinterpret_cast<float4*>(out + (size_t)i * HR + tid * 4) = o;
    }
}

// ---------------------------------------------------------------------------
extern "C" void kernel_launch(void* const* d_in, const int* in_sizes, int n_in,
                              void* d_out, int out_size)
{
    const float* node = (const float*)d_in[0];   // [4096,512]
    const float* adj  = (const float*)d_in[1];   // [4096,4096]
    const float* W    = (const float*)d_in[2];   // [8,512,64]
    const float* att  = (const float*)d_in[3];   // [8,128]
    const float* bias = (const float*)d_in[4];   // [4096,4096]
    float* out = (float*)d_out;                  // [4096,512]

    cudaFuncSetAttribute(gemm_mma_kernel,
                         cudaFuncAttributeMaxDynamicSharedMemorySize, 2 * STAGE);

    compact_pre_kernel<<<NN + (NN * FF / 8 + HR * FF / 4) / 256, 256>>>(adj, node, W);
    gemm_mma_kernel<<<dim3(HR / 128, NN / 128), 256, 2 * STAGE>>>(att);
    gat_row_kernel<<<NN, 256>>>(bias, out);
}